// round 2
// baseline (speedup 1.0000x reference)
#include <cuda_runtime.h>
#include <cuda_bf16.h>
#include <cstddef>

#define BATCH    256
#define DATA_DIM 8192
#define NNZ      256
#define QK       64
#define EMB      63
#define NSUB     8
#define K0S      260   // stride (floats) for transposed k0; 260 mod 32 = 4 -> conflict-free LDS.128

// Precomputed per-row projections of the embedding table (row 0 = padding row),
// stored as float4 rows of 16 (=64 floats).
__device__ float4 g_Q0T[(DATA_DIM + 1) * 16];
__device__ float4 g_K0T[(DATA_DIM + 1) * 16];

// packed f32x2 FMA: acc = a*b + acc (two independent fp32 lanes)
__device__ __forceinline__ void fma2(unsigned long long& acc,
                                     unsigned long long a,
                                     unsigned long long b) {
    asm("fma.rn.f32x2 %0, %1, %2, %0;" : "+l"(acc) : "l"(a), "l"(b));
}
__device__ __forceinline__ float hsum2(unsigned long long a) {
    return __uint_as_float((unsigned)a) + __uint_as_float((unsigned)(a >> 32));
}

// ---------------------------------------------------------------------------
// Kernel P: Q0T[p][d] = bq[d] + sum_e embed[p][e] * Wq[d][e+1]   (same for K)
// Grid: 513 blocks x 256 threads; block covers 16 table rows; thread = (row, 4 d's).
// ---------------------------------------------------------------------------
__global__ void __launch_bounds__(256)
precompute_kernel(const float* __restrict__ embed,
                  const float* __restrict__ Wq,
                  const float* __restrict__ bq,
                  const float* __restrict__ Wk,
                  const float* __restrict__ bk) {
    __shared__ __align__(16) float WqT[64 * 64];  // [e][d]
    __shared__ __align__(16) float WkT[64 * 64];
    __shared__ __align__(16) float es[16 * 64];

    const int tid = threadIdx.x;
    for (int i = tid; i < 4096; i += 256) {
        int d = i >> 6, e = i & 63;
        WqT[e * 64 + d] = Wq[i];
        WkT[e * 64 + d] = Wk[i];
    }
    const int p0 = blockIdx.x * 16;
    for (int i = tid; i < 16 * 63; i += 256) {
        int rr = i / 63, e = i - rr * 63;
        int p = p0 + rr;
        es[rr * 64 + e] = (p <= DATA_DIM) ? embed[(size_t)p * EMB + e] : 0.0f;
    }
    __syncthreads();

    const int r = tid >> 4, d4 = tid & 15;
    const int p = p0 + r;
    if (p <= DATA_DIM) {
        float4 aq = reinterpret_cast<const float4*>(bq)[d4];
        float4 ak = reinterpret_cast<const float4*>(bk)[d4];
#pragma unroll
        for (int e = 0; e < EMB; ++e) {
            float ev = es[r * 64 + e];
            float4 wq = *reinterpret_cast<const float4*>(&WqT[(e + 1) * 64 + 4 * d4]);
            float4 wk = *reinterpret_cast<const float4*>(&WkT[(e + 1) * 64 + 4 * d4]);
            aq.x += ev * wq.x; aq.y += ev * wq.y; aq.z += ev * wq.z; aq.w += ev * wq.w;
            ak.x += ev * wk.x; ak.y += ev * wk.y; ak.z += ev * wk.z; ak.w += ev * wk.w;
        }
        g_Q0T[(size_t)p * 16 + d4] = aq;
        g_K0T[(size_t)p * 16 + d4] = ak;
    }
}

// ---------------------------------------------------------------------------
// Kernel C: per-batch condense + RK4 integration + scatter of both planes.
// One block per batch, 256 threads (thread i owns position i).
// ---------------------------------------------------------------------------
struct SmemC {
    __align__(16) float k0[64 * K0S];   // transposed k0 [d][i]
    __align__(16) float wsh[NNZ];
    __align__(16) float s[QK];
    __align__(16) float mpart[256];
    __align__(16) float red1[8];        // per-warp w^2 partials
    __align__(16) float red2[8];        // per-warp w*f partials
    __align__(16) float c1p[2];         // a.s partials (2 warps of the s-step)
    __align__(16) float val[NNZ];
    int   idx[NNZ];
    int   wscan[8];
};

extern __shared__ unsigned char smem_raw[];

__global__ void __launch_bounds__(256, 2)
integrate_kernel(const float* __restrict__ t,
                 const float* __restrict__ x,
                 const float* __restrict__ Wq,
                 const float* __restrict__ Wk,
                 float* __restrict__ out) {
    SmemC* sm = reinterpret_cast<SmemC*>(smem_raw);
    const int tid  = threadIdx.x;
    const int b    = blockIdx.x;
    const int lane = tid & 31;
    const int wid  = tid >> 5;

    // ---- Phase 0: zero this block's two output rows (replaces host memset) ----
    {
        float4 z = make_float4(0.f, 0.f, 0.f, 0.f);
        float4* o4 = reinterpret_cast<float4*>(out);
        for (int i = tid; i < 2048; i += 256) {
            o4[(size_t)b * 2048 + i] = z;
            o4[(size_t)(BATCH + b) * 2048 + i] = z;
        }
    }

    // ---- Phase 1+2: direct-global scan + order-preserving compaction ----
    // Thread t scans x[b][32t .. 32t+31].
    float xr[32];
    {
        const float4* xrow4 = reinterpret_cast<const float4*>(x + (size_t)b * DATA_DIM) + tid * 8;
#pragma unroll
        for (int j = 0; j < 8; ++j) {
            float4 f = xrow4[j];
            xr[4 * j + 0] = f.x; xr[4 * j + 1] = f.y;
            xr[4 * j + 2] = f.z; xr[4 * j + 3] = f.w;
        }
    }
    if (tid < NNZ) { sm->val[tid] = 0.0f; sm->idx[tid] = 0; }

    int cnt = 0;
#pragma unroll
    for (int j = 0; j < 32; ++j) cnt += (xr[j] != 0.0f) ? 1 : 0;
    int inc = cnt;
#pragma unroll
    for (int o = 1; o < 32; o <<= 1) {
        int u = __shfl_up_sync(0xffffffffu, inc, o);
        if (lane >= o) inc += u;
    }
    if (lane == 31) sm->wscan[wid] = inc;
    __syncthreads();
    int woff = 0;
#pragma unroll
    for (int wdx = 0; wdx < 8; ++wdx) woff += (wdx < wid) ? sm->wscan[wdx] : 0;
    int o = woff + inc - cnt;  // exclusive prefix
#pragma unroll
    for (int j = 0; j < 32; ++j) {
        float v = xr[j];
        if (v != 0.0f && o < NNZ) {
            sm->val[o] = v;
            sm->idx[o] = tid * 32 + j;
            ++o;
        }
    }
    __syncthreads();

    // ---- Phase 3: gather q0 (registers, packed pairs) / k0 (shared, transposed) ----
    const int p     = sm->idx[tid] + 1;
    const float myv = sm->val[tid];

    // scatter initial plane (t=0); ordered after phase-0 zero by the syncthreads above
    out[(size_t)b * DATA_DIM + (p - 1)] = myv;

    ulonglong2 q0p[16];
    {
        const ulonglong2* qrow = reinterpret_cast<const ulonglong2*>(g_Q0T + (size_t)p * 16);
#pragma unroll
        for (int i = 0; i < 16; ++i) q0p[i] = qrow[i];
        const float4* krow = g_K0T + (size_t)p * 16;
#pragma unroll
        for (int i = 0; i < 16; ++i) {
            float4 f = krow[i];
            int d = 4 * i;
            sm->k0[(d + 0) * K0S + tid] = f.x;
            sm->k0[(d + 1) * K0S + tid] = f.y;
            sm->k0[(d + 2) * K0S + tid] = f.z;
            sm->k0[(d + 3) * K0S + tid] = f.w;
        }
    }

    // a[d], b[d] register-resident in the 64 s-step threads
    float avd = 0.0f, bvd = 0.0f;
    if (tid < QK) { avd = Wq[tid * 64]; bvd = Wk[tid * 64]; }

    const float dt = (t[1] - t[0]) * (1.0f / (float)NSUB);
    const int dd = tid & 63, cc = tid >> 6;
    const ulonglong2* krowsh = reinterpret_cast<const ulonglong2*>(sm->k0 + dd * K0S + cc * 64);
    const ulonglong2* wvp    = reinterpret_cast<const ulonglong2*>(sm->wsh + cc * 64);
    const ulonglong2* svp    = reinterpret_cast<const ulonglong2*>(sm->s);

    // stage: publish w + per-warp w^2 partial (caller must __syncthreads after)
    auto stage = [&](float w) {
        sm->wsh[tid] = w;
        float w2 = w * w;
#pragma unroll
        for (int o2 = 16; o2 > 0; o2 >>= 1) w2 += __shfl_xor_sync(0xffffffffu, w2, o2);
        if (lane == 0) sm->red1[wid] = w2;
    };

    // dxdt(w) = w * (f - g),  f_i = (w_i*c1 + q0_i.s)/8,
    // s = S2*b + K0^T w,  c1 = a.s,  g = sum_j w_j f_j
    // precondition: wsh/red1 staged and synced
    auto dxdt = [&](float w) -> float {
        // partial of m[d] over chunk cc: 16 x (2 fma2) on packed pairs
        unsigned long long a0 = 0ull, a1 = 0ull;
#pragma unroll
        for (int j = 0; j < 16; ++j) {
            ulonglong2 kv = krowsh[j];
            ulonglong2 wv = wvp[j];
            fma2(a0, kv.x, wv.x);
            fma2(a1, kv.y, wv.y);
        }
        sm->mpart[tid] = hsum2(a0) + hsum2(a1);
        __syncthreads();

        if (tid < QK) {
            float4 r1a = *reinterpret_cast<const float4*>(&sm->red1[0]);
            float4 r1b = *reinterpret_cast<const float4*>(&sm->red1[4]);
            float S2 = (r1a.x + r1a.y) + (r1a.z + r1a.w) + (r1b.x + r1b.y) + (r1b.z + r1b.w);
            float m = sm->mpart[tid] + sm->mpart[tid + 64] +
                      sm->mpart[tid + 128] + sm->mpart[tid + 192];
            float sv = S2 * bvd + m;
            sm->s[tid] = sv;
            float cp = avd * sv;
#pragma unroll
            for (int o2 = 16; o2 > 0; o2 >>= 1) cp += __shfl_xor_sync(0xffffffffu, cp, o2);
            if (lane == 0) sm->c1p[wid] = cp;   // wid = 0 or 1 here
        }
        __syncthreads();

        unsigned long long q0 = 0ull, q1 = 0ull;
#pragma unroll
        for (int j = 0; j < 16; ++j) {
            ulonglong2 sv = svp[j];
            fma2(q0, q0p[j].x, sv.x);
            fma2(q1, q0p[j].y, sv.y);
        }
        float qdot = hsum2(q0) + hsum2(q1);
        float c1 = sm->c1p[0] + sm->c1p[1];
        float f  = (c1 * w + qdot) * 0.125f;   // 1/sqrt(64)

        float wf = w * f;
#pragma unroll
        for (int o2 = 16; o2 > 0; o2 >>= 1) wf += __shfl_xor_sync(0xffffffffu, wf, o2);
        if (lane == 0) sm->red2[wid] = wf;
        __syncthreads();
        float4 r2a = *reinterpret_cast<const float4*>(&sm->red2[0]);
        float4 r2b = *reinterpret_cast<const float4*>(&sm->red2[4]);
        float g = (r2a.x + r2a.y) + (r2a.z + r2a.w) + (r2b.x + r2b.y) + (r2b.z + r2b.w);

        return w * (f - g);
    };

    float vcur = myv;
    stage(vcur);
    __syncthreads();

    // ---- Phase 4: 8 RK4 substeps over [t0, t1] ----
    for (int stp = 0; stp < NSUB; ++stp) {
        float k1 = dxdt(vcur);
        float w2s = vcur + 0.5f * dt * k1;
        stage(w2s); __syncthreads();
        float k2 = dxdt(w2s);
        float w3s = vcur + 0.5f * dt * k2;
        stage(w3s); __syncthreads();
        float k3 = dxdt(w3s);
        float w4s = vcur + dt * k3;
        stage(w4s); __syncthreads();
        float k4 = dxdt(w4s);
        vcur += dt * (1.0f / 6.0f) * (k1 + 2.0f * k2 + 2.0f * k3 + k4);
        stage(vcur); __syncthreads();
    }

    // scatter final plane (t=1)
    out[(size_t)BATCH * DATA_DIM + (size_t)b * DATA_DIM + (p - 1)] = vcur;
}

// ---------------------------------------------------------------------------
// kernel_launch
// ---------------------------------------------------------------------------
extern "C" void kernel_launch(void* const* d_in, const int* in_sizes, int n_in,
                              void* d_out, int out_size) {
    const float* t     = (const float*)d_in[0];
    const float* x     = (const float*)d_in[1];
    const float* embed = (const float*)d_in[2];
    const float* Wq    = (const float*)d_in[3];
    const float* bq    = (const float*)d_in[4];
    const float* Wk    = (const float*)d_in[5];
    const float* bk    = (const float*)d_in[6];
    float* out = (float*)d_out;

    cudaFuncSetAttribute(integrate_kernel,
                         cudaFuncAttributeMaxDynamicSharedMemorySize,
                         (int)sizeof(SmemC));

    precompute_kernel<<<(DATA_DIM + 1 + 15) / 16, 256>>>(embed, Wq, bq, Wk, bk);
    integrate_kernel<<<BATCH, 256, sizeof(SmemC)>>>(t, x, Wq, Wk, out);
}